// round 6
// baseline (speedup 1.0000x reference)
#include <cuda_runtime.h>
#include <math.h>

#define HDIM   256
#define H3     768
#define MSGD   685
#define UMAX   65536
#define NNMAX  200000

// Scratch: __device__ globals (no cudaMalloc allowed)
__device__ float g_gi[(size_t)UMAX * H3];
__device__ float g_gh[(size_t)UMAX * H3];
__device__ int   g_idx[UMAX];
__device__ int   g_win[NNMAX];

// ---------------------------------------------------------------------------
__global__ void cvt_idx_kernel(const unsigned* __restrict__ raw, int U, int nnodes) {
    bool is64 = (raw[1] == 0u && raw[3] == 0u && raw[5] == 0u && raw[7] == 0u);
    int u = blockIdx.x * blockDim.x + threadIdx.x;
    if (u < U) {
        int v = is64 ? (int)raw[2 * (size_t)u] : (int)raw[u];
        if (v < 0) v = 0;
        if (v >= nnodes) v = nnodes - 1;
        g_idx[u] = v;
    }
}

__global__ void init_win_kernel(int nnodes) {
    int i = blockIdx.x * blockDim.x + threadIdx.x;
    if (i < nnodes) g_win[i] = -1;
}

__global__ void vote_kernel(int U) {
    int u = blockIdx.x * blockDim.x + threadIdx.x;
    if (u < U) atomicMax(&g_win[g_idx[u]], u);   // last-update-wins
}

__global__ void copy_out_kernel(const float4* __restrict__ src,
                                float4* __restrict__ dst, long long n4) {
    long long i = (long long)blockIdx.x * blockDim.x + threadIdx.x;
    long long stride = (long long)gridDim.x * blockDim.x;
    for (; i < n4; i += stride) dst[i] = src[i];
}

// ---------------------------------------------------------------------------
// C[M,N] = Arow(m) . W[n,:] + bias[n], Arow(m) = A + (ridx? ridx[m] : m)*K
// BM=128, BN=64, BK=16, 256 threads, 8x4 micro-tile.
__global__ __launch_bounds__(256)
void gemm_tn2(const float* __restrict__ A, const int* __restrict__ ridx,
              const float* __restrict__ W, const float* __restrict__ bias,
              float* __restrict__ C, int M, int N, int K) {
    constexpr int BM = 128, BN = 64, BK = 16;
    __shared__ float As[BK][BM + 8];
    __shared__ float Ws[BK][BN + 8];

    const int t  = threadIdx.x;
    const int m0 = blockIdx.y * BM;
    const int n0 = blockIdx.x * BN;
    const int lk = t & 15;
    const int lr = t >> 4;
    const int tm = t & 15;
    const int tn = t >> 4;

    size_t abase[8];
    #pragma unroll
    for (int i = 0; i < 8; i++) {
        int row = m0 + lr + 16 * i;
        if (row >= M) row = M - 1;
        int src = (ridx != nullptr) ? ridx[row] : row;
        abase[i] = (size_t)src * K;
    }
    size_t wbase[4];
    #pragma unroll
    for (int i = 0; i < 4; i++)
        wbase[i] = (size_t)(n0 + lr + 16 * i) * K;

    float acc[8][4];
    #pragma unroll
    for (int i = 0; i < 8; i++)
        #pragma unroll
        for (int j = 0; j < 4; j++) acc[i][j] = 0.f;

    for (int k0 = 0; k0 < K; k0 += BK) {
        const int k = k0 + lk;
        const bool kin = (k < K);
        #pragma unroll
        for (int i = 0; i < 8; i++)
            As[lk][lr + 16 * i] = kin ? A[abase[i] + k] : 0.f;
        #pragma unroll
        for (int i = 0; i < 4; i++)
            Ws[lk][lr + 16 * i] = kin ? W[wbase[i] + k] : 0.f;
        __syncthreads();

        #pragma unroll
        for (int kk = 0; kk < BK; kk++) {
            float a[8], w[4];
            #pragma unroll
            for (int i = 0; i < 8; i++) a[i] = As[kk][tm * 8 + i];
            #pragma unroll
            for (int j = 0; j < 4; j++) w[j] = Ws[kk][tn * 4 + j];
            #pragma unroll
            for (int i = 0; i < 8; i++)
                #pragma unroll
                for (int j = 0; j < 4; j++)
                    acc[i][j] = fmaf(a[i], w[j], acc[i][j]);
        }
        __syncthreads();
    }

    #pragma unroll
    for (int i = 0; i < 8; i++) {
        const int m = m0 + tm * 8 + i;
        if (m >= M) continue;
        #pragma unroll
        for (int j = 0; j < 4; j++) {
            const int n = n0 + tn * 4 + j;
            C[(size_t)m * N + n] = acc[i][j] + bias[n];
        }
    }
}

// ---------------------------------------------------------------------------
__global__ void gru_scatter_kernel(const float* __restrict__ mem,
                                   float* __restrict__ out, long long total) {
    long long i = (long long)blockIdx.x * blockDim.x + threadIdx.x;
    long long stride = (long long)gridDim.x * blockDim.x;
    for (; i < total; i += stride) {
        int u = (int)(i >> 8);
        int c = (int)(i & 255);
        int node = g_idx[u];
        if (g_win[node] != u) continue;   // last-update-wins

        const float* gi = g_gi + (size_t)u * H3;
        const float* gh = g_gh + (size_t)u * H3;
        float h   = mem[(size_t)node * HDIM + c];

        float i_r = gi[c],            h_r = gh[c];
        float i_z = gi[HDIM + c],     h_z = gh[HDIM + c];
        float i_n = gi[2 * HDIM + c], h_n = gh[2 * HDIM + c];

        float r = 1.f / (1.f + expf(-(i_r + h_r)));
        float z = 1.f / (1.f + expf(-(i_z + h_z)));
        float n = tanhf(i_n + r * h_n);
        float hn = (1.f - z) * n + z * h;

        out[(size_t)node * HDIM + c] = hn;
    }
}

// ---------------------------------------------------------------------------
extern "C" void kernel_launch(void* const* d_in, const int* in_sizes, int n_in,
                              void* d_out, int out_size) {
    // ---- CRITICAL FIX: resolve true device addresses of __device__ scratch.
    // Host-decayed symbol pointers are the HOST shadow (silently ATS-accessible
    // on GB300!), not the device arrays. Must use cudaGetSymbolAddress.
    void *p_gi = nullptr, *p_gh = nullptr, *p_idx = nullptr;
    cudaGetSymbolAddress(&p_gi,  g_gi);
    cudaGetSymbolAddress(&p_gh,  g_gh);
    cudaGetSymbolAddress(&p_idx, g_idx);
    float* d_gi  = (float*)p_gi;
    float* d_gh  = (float*)p_gh;
    int*   d_idx = (int*)p_idx;

    // ---- size-based input identification (immune to argument ordering) ----
    const float*    memory   = nullptr;
    const float*    messages = nullptr;
    const unsigned* node_raw = nullptr;
    const float*    W_ih     = nullptr;
    const float*    W_hh     = nullptr;
    const float*    b_ih     = nullptr;
    const float*    b_hh     = nullptr;

    for (int i = 0; i < n_in; i++) {
        long long s = in_sizes[i];
        const void* p = d_in[i];
        if (s == (long long)out_size)            memory   = (const float*)p;
        else if (s == (long long)H3 * MSGD)      W_ih     = (const float*)p;
        else if (s == (long long)H3 * HDIM)      W_hh     = (const float*)p;
        else if (s == H3) { if (!b_ih) b_ih = (const float*)p; else b_hh = (const float*)p; }
        else if (s == UMAX || s == 2 * UMAX)     node_raw = (const unsigned*)p;
        else if (s % MSGD == 0 && s > (long long)H3 * MSGD) messages = (const float*)p;
    }
    if (!memory)   memory   = (const float*)   d_in[0];
    if (!messages) messages = (const float*)   d_in[1];
    if (!node_raw) node_raw = (const unsigned*)d_in[2];
    if (!W_ih)     W_ih     = (const float*)   d_in[3];
    if (!W_hh)     W_hh     = (const float*)   d_in[4];
    if (!b_ih)     b_ih     = (const float*)   d_in[5];
    if (!b_hh)     b_hh     = (const float*)   d_in[6];

    const int nnodes = out_size / HDIM;
    int U = UMAX;
    for (int i = 0; i < n_in; i++)
        if (d_in[i] == (const void*)messages) { U = in_sizes[i] / MSGD; break; }

    // 0) normalize indices
    cvt_idx_kernel<<<(U + 255) / 256, 256>>>(node_raw, U, nnodes);

    // 1) out = memory
    float* out = (float*)d_out;
    copy_out_kernel<<<2048, 256>>>((const float4*)memory, (float4*)out,
                                   (long long)out_size / 4);

    // 2) winner vote (last update per node wins)
    init_win_kernel<<<(nnodes + 255) / 256, 256>>>(nnodes);
    vote_kernel<<<(U + 255) / 256, 256>>>(U);

    // 3) gi = messages @ W_ih^T + b_ih   [U, 768], K=685
    {
        dim3 grid(H3 / 64, (U + 127) / 128);
        gemm_tn2<<<grid, 256>>>(messages, nullptr, W_ih, b_ih, d_gi, U, H3, MSGD);
    }
    // 4) gh = memory[idx] @ W_hh^T + b_hh  (gather fused via indirect A rows)
    {
        dim3 grid(H3 / 64, (U + 127) / 128);
        gemm_tn2<<<grid, 256>>>(memory, d_idx, W_hh, b_hh, d_gh, U, H3, HDIM);
    }

    // 5) GRU + scatter winners
    gru_scatter_kernel<<<4096, 256>>>(memory, out, (long long)U * HDIM);
}

// round 8
// speedup vs baseline: 3.6486x; 3.6486x over previous
#include <cuda_runtime.h>
#include <cuda_bf16.h>
#include <mma.h>
#include <math.h>
#include <cstdint>

using namespace nvcuda;

#define HDIM   256
#define H3     768
#define MSGD   685
#define UMAX   65536
#define NNMAX  200000

// Scratch (device globals; host resolves via cudaGetSymbolAddress)
__device__ float g_gi[(size_t)UMAX * H3];
__device__ float g_gh[(size_t)UMAX * H3];
__device__ int   g_idx[UMAX];
__device__ int   g_win[NNMAX];

// ============================ small kernels ============================
__global__ void cvt_idx_kernel(const unsigned* __restrict__ raw, int U, int nnodes) {
    bool is64 = (raw[1] == 0u && raw[3] == 0u && raw[5] == 0u && raw[7] == 0u);
    int u = blockIdx.x * blockDim.x + threadIdx.x;
    if (u < U) {
        int v = is64 ? (int)raw[2 * (size_t)u] : (int)raw[u];
        if (v < 0) v = 0;
        if (v >= nnodes) v = nnodes - 1;
        g_idx[u] = v;
    }
}
__global__ void init_win_kernel(int nnodes) {
    int i = blockIdx.x * blockDim.x + threadIdx.x;
    if (i < nnodes) g_win[i] = -1;
}
__global__ void vote_kernel(int U) {
    int u = blockIdx.x * blockDim.x + threadIdx.x;
    if (u < U) atomicMax(&g_win[g_idx[u]], u);   // last-update-wins
}
__global__ void copy_out_kernel(const float4* __restrict__ src,
                                float4* __restrict__ dst, long long n4) {
    long long i = (long long)blockIdx.x * blockDim.x + threadIdx.x;
    long long stride = (long long)gridDim.x * blockDim.x;
    for (; i < n4; i += stride) dst[i] = src[i];
}

// ============================================================================
// C[M,768] tile = Arow(m)[*,K] @ W[768,K]^T  (NO bias; bias folded into GRU)
// bf16 2-term split via WMMA: acc += Ahi*Bhi + Ahi*Blo + Alo*Bhi.
// CTA: 128(M) x 64(N), 8 warps of 32x32, K staged in chunks of 32.
#define LDA 40   // padded bf16 row stride (32 + 8)
__global__ __launch_bounds__(256)
void gemm_wmma_split(const float* __restrict__ A, const int* __restrict__ ridx,
                     const float* __restrict__ W, float* __restrict__ C,
                     int M, int K, int nchunks) {
    __shared__ __nv_bfloat16 Ah[128 * LDA], Al[128 * LDA];
    __shared__ __nv_bfloat16 Bh[64 * LDA],  Bl[64 * LDA];

    const int t   = threadIdx.x;
    const int wid = t >> 5;
    const int m0  = blockIdx.y * 128;
    const int n0  = blockIdx.x * 64;
    const int wm  = (wid >> 1) * 32;   // warp M offset within tile
    const int wn  = (wid & 1) * 32;    // warp N offset within tile

    wmma::fragment<wmma::accumulator, 16, 16, 16, float> acc[2][2];
    #pragma unroll
    for (int i = 0; i < 2; i++)
        #pragma unroll
        for (int j = 0; j < 2; j++) wmma::fill_fragment(acc[i][j], 0.0f);

    // Precompute A row pointers for this thread's loader lanes
    const int lrow = t >> 3;           // 0..31
    const int lc4  = (t & 7) * 4;      // 0,4,...,28

    for (int c = 0; c < nchunks; ++c) {
        const int k0 = c * 32;

        // ---- A: 128 rows x 32 k (4 passes of 32 rows) ----
        #pragma unroll
        for (int p = 0; p < 4; p++) {
            int row = p * 32 + lrow;
            int gr = m0 + row; if (gr >= M) gr = M - 1;
            const float* ap = A + (size_t)(ridx ? ridx[gr] : gr) * K;
            float x[4];
            #pragma unroll
            for (int j = 0; j < 4; j++) {
                int kk = k0 + lc4 + j;
                x[j] = (kk < K) ? __ldg(ap + kk) : 0.f;
            }
            uint32_t hu[2], lu[2];
            #pragma unroll
            for (int q = 0; q < 2; q++) {
                __nv_bfloat16 h0 = __float2bfloat16(x[2*q]);
                __nv_bfloat16 h1 = __float2bfloat16(x[2*q+1]);
                __nv_bfloat16 l0 = __float2bfloat16(x[2*q]   - __bfloat162float(h0));
                __nv_bfloat16 l1 = __float2bfloat16(x[2*q+1] - __bfloat162float(h1));
                hu[q] = ((uint32_t)__bfloat16_as_ushort(h1) << 16) | __bfloat16_as_ushort(h0);
                lu[q] = ((uint32_t)__bfloat16_as_ushort(l1) << 16) | __bfloat16_as_ushort(l0);
            }
            int off = row * LDA + lc4;
            *(uint2*)(Ah + off) = make_uint2(hu[0], hu[1]);
            *(uint2*)(Al + off) = make_uint2(lu[0], lu[1]);
        }
        // ---- B: 64 rows x 32 k (2 passes) ----
        #pragma unroll
        for (int p = 0; p < 2; p++) {
            int row = p * 32 + lrow;
            const float* wp = W + (size_t)(n0 + row) * K;
            float x[4];
            #pragma unroll
            for (int j = 0; j < 4; j++) {
                int kk = k0 + lc4 + j;
                x[j] = (kk < K) ? __ldg(wp + kk) : 0.f;
            }
            uint32_t hu[2], lu[2];
            #pragma unroll
            for (int q = 0; q < 2; q++) {
                __nv_bfloat16 h0 = __float2bfloat16(x[2*q]);
                __nv_bfloat16 h1 = __float2bfloat16(x[2*q+1]);
                __nv_bfloat16 l0 = __float2bfloat16(x[2*q]   - __bfloat162float(h0));
                __nv_bfloat16 l1 = __float2bfloat16(x[2*q+1] - __bfloat162float(h1));
                hu[q] = ((uint32_t)__bfloat16_as_ushort(h1) << 16) | __bfloat16_as_ushort(h0);
                lu[q] = ((uint32_t)__bfloat16_as_ushort(l1) << 16) | __bfloat16_as_ushort(l0);
            }
            int off = row * LDA + lc4;
            *(uint2*)(Bh + off) = make_uint2(hu[0], hu[1]);
            *(uint2*)(Bl + off) = make_uint2(lu[0], lu[1]);
        }
        __syncthreads();

        // ---- 2 k-steps of 16 ----
        #pragma unroll
        for (int ks = 0; ks < 2; ks++) {
            const int kk = ks * 16;
            wmma::fragment<wmma::matrix_a, 16, 16, 16, __nv_bfloat16, wmma::row_major> ah[2], al[2];
            wmma::fragment<wmma::matrix_b, 16, 16, 16, __nv_bfloat16, wmma::col_major> bh[2], bl[2];
            #pragma unroll
            for (int i = 0; i < 2; i++) {
                wmma::load_matrix_sync(ah[i], Ah + (wm + i * 16) * LDA + kk, LDA);
                wmma::load_matrix_sync(al[i], Al + (wm + i * 16) * LDA + kk, LDA);
            }
            #pragma unroll
            for (int j = 0; j < 2; j++) {
                wmma::load_matrix_sync(bh[j], Bh + (wn + j * 16) * LDA + kk, LDA);
                wmma::load_matrix_sync(bl[j], Bl + (wn + j * 16) * LDA + kk, LDA);
            }
            #pragma unroll
            for (int i = 0; i < 2; i++)
                #pragma unroll
                for (int j = 0; j < 2; j++) {
                    wmma::mma_sync(acc[i][j], ah[i], bh[j], acc[i][j]);
                    wmma::mma_sync(acc[i][j], ah[i], bl[j], acc[i][j]);
                    wmma::mma_sync(acc[i][j], al[i], bh[j], acc[i][j]);
                }
        }
        __syncthreads();
    }

    // ---- epilogue: direct store to C (no bias) ----
    #pragma unroll
    for (int i = 0; i < 2; i++) {
        int row = m0 + wm + i * 16;
        if (row + 16 > M) continue;
        #pragma unroll
        for (int j = 0; j < 2; j++)
            wmma::store_matrix_sync(C + (size_t)row * H3 + n0 + wn + j * 16,
                                    acc[i][j], H3, wmma::mem_row_major);
    }
}

// ============================================================================
// GRU elementwise + scatter; biases folded here (gi/gh hold raw GEMM outputs).
__global__ void gru_scatter_kernel(const float* __restrict__ mem,
                                   const float* __restrict__ b_ih,
                                   const float* __restrict__ b_hh,
                                   float* __restrict__ out, long long total) {
    long long i = (long long)blockIdx.x * blockDim.x + threadIdx.x;
    long long stride = (long long)gridDim.x * blockDim.x;
    for (; i < total; i += stride) {
        int u = (int)(i >> 8);
        int c = (int)(i & 255);
        int node = g_idx[u];
        if (g_win[node] != u) continue;   // last-update-wins

        const float* gi = g_gi + (size_t)u * H3;
        const float* gh = g_gh + (size_t)u * H3;
        float h = mem[(size_t)node * HDIM + c];

        float i_r = gi[c]            + __ldg(b_ih + c);
        float i_z = gi[HDIM + c]     + __ldg(b_ih + HDIM + c);
        float i_n = gi[2 * HDIM + c] + __ldg(b_ih + 2 * HDIM + c);
        float h_r = gh[c]            + __ldg(b_hh + c);
        float h_z = gh[HDIM + c]     + __ldg(b_hh + HDIM + c);
        float h_n = gh[2 * HDIM + c] + __ldg(b_hh + 2 * HDIM + c);

        float r = 1.f / (1.f + expf(-(i_r + h_r)));
        float z = 1.f / (1.f + expf(-(i_z + h_z)));
        float n = tanhf(i_n + r * h_n);
        out[(size_t)node * HDIM + c] = (1.f - z) * n + z * h;
    }
}

// ============================================================================
extern "C" void kernel_launch(void* const* d_in, const int* in_sizes, int n_in,
                              void* d_out, int out_size) {
    void *p_gi = nullptr, *p_gh = nullptr, *p_idx = nullptr;
    cudaGetSymbolAddress(&p_gi,  g_gi);
    cudaGetSymbolAddress(&p_gh,  g_gh);
    cudaGetSymbolAddress(&p_idx, g_idx);
    float* d_gi  = (float*)p_gi;
    float* d_gh  = (float*)p_gh;
    int*   d_idx = (int*)p_idx;

    // size-based input identification (immune to argument ordering)
    const float *memory = nullptr, *messages = nullptr, *W_ih = nullptr,
                *W_hh = nullptr, *b_ih = nullptr, *b_hh = nullptr;
    const unsigned* node_raw = nullptr;
    for (int i = 0; i < n_in; i++) {
        long long s = in_sizes[i];
        const void* p = d_in[i];
        if (s == (long long)out_size)            memory   = (const float*)p;
        else if (s == (long long)H3 * MSGD)      W_ih     = (const float*)p;
        else if (s == (long long)H3 * HDIM)      W_hh     = (const float*)p;
        else if (s == H3) { if (!b_ih) b_ih = (const float*)p; else b_hh = (const float*)p; }
        else if (s == UMAX || s == 2 * UMAX)     node_raw = (const unsigned*)p;
        else if (s % MSGD == 0 && s > (long long)H3 * MSGD) messages = (const float*)p;
    }
    if (!memory)   memory   = (const float*)   d_in[0];
    if (!messages) messages = (const float*)   d_in[1];
    if (!node_raw) node_raw = (const unsigned*)d_in[2];
    if (!W_ih)     W_ih     = (const float*)   d_in[3];
    if (!W_hh)     W_hh     = (const float*)   d_in[4];
    if (!b_ih)     b_ih     = (const float*)   d_in[5];
    if (!b_hh)     b_hh     = (const float*)   d_in[6];

    const int nnodes = out_size / HDIM;
    int U = UMAX;
    for (int i = 0; i < n_in; i++)
        if (d_in[i] == (const void*)messages) { U = in_sizes[i] / MSGD; break; }

    cvt_idx_kernel<<<(U + 255) / 256, 256>>>(node_raw, U, nnodes);

    float* out = (float*)d_out;
    copy_out_kernel<<<2048, 256>>>((const float4*)memory, (float4*)out,
                                   (long long)out_size / 4);

    init_win_kernel<<<(nnodes + 255) / 256, 256>>>(nnodes);
    vote_kernel<<<(U + 255) / 256, 256>>>(U);

    // gi = messages @ W_ih^T   [U,768], K=685 (22 chunks of 32)
    {
        dim3 grid(H3 / 64, (U + 127) / 128);
        gemm_wmma_split<<<grid, 256>>>(messages, nullptr, W_ih, d_gi,
                                       U, MSGD, (MSGD + 31) / 32);
    }
    // gh = memory[idx] @ W_hh^T   [U,768], K=256 (8 chunks), gather fused
    {
        dim3 grid(H3 / 64, (U + 127) / 128);
        gemm_wmma_split<<<grid, 256>>>(memory, d_idx, W_hh, d_gh,
                                       U, HDIM, HDIM / 32);
    }

    gru_scatter_kernel<<<4096, 256>>>(memory, b_ih, b_hh, out, (long long)U * HDIM);
}

// round 9
// speedup vs baseline: 4.7040x; 1.2893x over previous
#include <cuda_runtime.h>
#include <cuda_bf16.h>
#include <mma.h>
#include <math.h>
#include <cstdint>

using namespace nvcuda;

#define HDIM   256
#define H3     768
#define MSGD   685
#define KPADM  704          // 685 padded to multiple of 32
#define UMAX   65536
#define NNMAX  200000

// -------- device scratch (no cudaMalloc allowed) --------
__device__ float g_gi[(size_t)UMAX * H3];
__device__ float g_gh[(size_t)UMAX * H3];
__device__ __nv_bfloat16 g_mhi[(size_t)UMAX * KPADM];
__device__ __nv_bfloat16 g_mlo[(size_t)UMAX * KPADM];
__device__ __nv_bfloat16 g_hhi[(size_t)UMAX * HDIM];
__device__ __nv_bfloat16 g_hlo[(size_t)UMAX * HDIM];
__device__ __nv_bfloat16 g_w1hi[(size_t)H3 * KPADM];
__device__ __nv_bfloat16 g_w1lo[(size_t)H3 * KPADM];
__device__ __nv_bfloat16 g_w2hi[(size_t)H3 * HDIM];
__device__ __nv_bfloat16 g_w2lo[(size_t)H3 * HDIM];
__device__ int g_idx[UMAX];
__device__ int g_win[NNMAX];

// -------- ptx helpers --------
__device__ __forceinline__ uint32_t smem_u32(const void* p) {
    uint32_t a;
    asm("{ .reg .u64 t; cvta.to.shared.u64 t, %1; cvt.u32.u64 %0, t; }" : "=r"(a) : "l"(p));
    return a;
}
__device__ __forceinline__ void cp16(uint32_t d, const void* s) {
    asm volatile("cp.async.cg.shared.global [%0], [%1], 16;" :: "r"(d), "l"(s));
}
#define CP_COMMIT() asm volatile("cp.async.commit_group;" ::: "memory")
#define CP_WAIT(n)  asm volatile("cp.async.wait_group %0;" :: "n"(n) : "memory")

// ============================ small kernels ============================
__global__ void cvt_idx_kernel(const unsigned* __restrict__ raw, int U, int nnodes) {
    bool is64 = (raw[1] == 0u && raw[3] == 0u && raw[5] == 0u && raw[7] == 0u);
    int u = blockIdx.x * blockDim.x + threadIdx.x;
    if (u < U) {
        int v = is64 ? (int)raw[2 * (size_t)u] : (int)raw[u];
        if (v < 0) v = 0;
        if (v >= nnodes) v = nnodes - 1;
        g_idx[u] = v;
    }
}
__global__ void init_win_kernel(int nnodes) {
    int i = blockIdx.x * blockDim.x + threadIdx.x;
    if (i < nnodes) g_win[i] = -1;
}
__global__ void vote_kernel(int U) {
    int u = blockIdx.x * blockDim.x + threadIdx.x;
    if (u < U) atomicMax(&g_win[g_idx[u]], u);   // last-update-wins
}
__global__ void copy_out_kernel(const float4* __restrict__ src,
                                float4* __restrict__ dst, long long n4) {
    long long i = (long long)blockIdx.x * blockDim.x + threadIdx.x;
    long long stride = (long long)gridDim.x * blockDim.x;
    for (; i < n4; i += stride) dst[i] = src[i];
}

// fp32 [rows,K] -> bf16 hi/lo [rows,Kpad] (zero-padded)
__global__ void split_pad_kernel(const float* __restrict__ src,
                                 __nv_bfloat16* __restrict__ hi,
                                 __nv_bfloat16* __restrict__ lo,
                                 long long rows, int K, int Kpad) {
    long long total = rows * Kpad;
    long long i = (long long)blockIdx.x * blockDim.x + threadIdx.x;
    long long stride = (long long)gridDim.x * blockDim.x;
    for (; i < total; i += stride) {
        long long r = i / Kpad;
        int k = (int)(i - r * Kpad);
        float v = (k < K) ? __ldg(src + r * (long long)K + k) : 0.f;
        __nv_bfloat16 h = __float2bfloat16(v);
        hi[i] = h;
        lo[i] = __float2bfloat16(v - __bfloat162float(h));
    }
}
// gathered memory rows -> bf16 hi/lo [U,256]
__global__ void split_gather_kernel(const float* __restrict__ mem,
                                    __nv_bfloat16* __restrict__ hi,
                                    __nv_bfloat16* __restrict__ lo,
                                    long long total) {
    long long i = (long long)blockIdx.x * blockDim.x + threadIdx.x;
    long long stride = (long long)gridDim.x * blockDim.x;
    for (; i < total; i += stride) {
        int u = (int)(i >> 8);
        int c = (int)(i & 255);
        float v = __ldg(mem + (size_t)g_idx[u] * HDIM + c);
        __nv_bfloat16 h = __float2bfloat16(v);
        hi[i] = h;
        lo[i] = __float2bfloat16(v - __bfloat162float(h));
    }
}

// ============================================================================
// C[M,768] = A[M,Kpad](bf16 hi/lo) @ B[768,Kpad](bf16 hi/lo)^T  (no bias)
// CTA 128x128, 8 warps (4x2) of 32x64, BK=32, double-buffered cp.async.
// SMEM stage: Ah,Al,Bh,Bl each 128 rows x 40 elems (pad) x 2B = 10240B; x4 = 40960B; x2 stages.
#define LDS  40
#define MATB 10240
#define STGB 40960
__global__ __launch_bounds__(256)
void gemm_bf16x2(const __nv_bfloat16* __restrict__ Ahi, const __nv_bfloat16* __restrict__ Alo,
                 const __nv_bfloat16* __restrict__ Bhi, const __nv_bfloat16* __restrict__ Blo,
                 float* __restrict__ C, int M, int Kpad, int nchunks) {
    extern __shared__ char smem[];
    const uint32_t sb = smem_u32(smem);
    const int tid = threadIdx.x;
    const int wid = tid >> 5;
    const int m0 = blockIdx.y * 128;
    const int n0 = blockIdx.x * 128;
    const int wm = (wid & 3) * 32;
    const int wn = (wid >> 2) * 64;

    wmma::fragment<wmma::accumulator, 16, 16, 16, float> acc[2][4];
    #pragma unroll
    for (int i = 0; i < 2; i++)
        #pragma unroll
        for (int j = 0; j < 4; j++) wmma::fill_fragment(acc[i][j], 0.0f);

    // ---- async stage loader: 512 x 16B per matrix, 8 cp.async per thread ----
    auto issue = [&](int c, int s) {
        const int k0 = c * 32;
        const uint32_t base = sb + s * STGB;
        #pragma unroll
        for (int r = 0; r < 2; r++) {
            int id  = tid + 256 * r;
            int row = id >> 2;
            int seg = id & 3;
            uint32_t doff = row * (LDS * 2) + seg * 16;
            int gr = m0 + row; if (gr >= M) gr = M - 1;
            size_t ga = (size_t)gr * Kpad + k0 + seg * 8;
            cp16(base + doff,            Ahi + ga);
            cp16(base + MATB + doff,     Alo + ga);
            size_t wa = (size_t)(n0 + row) * Kpad + k0 + seg * 8;
            cp16(base + 2 * MATB + doff, Bhi + wa);
            cp16(base + 3 * MATB + doff, Blo + wa);
        }
        CP_COMMIT();
    };

    issue(0, 0);
    for (int c = 0; c < nchunks; c++) {
        if (c + 1 < nchunks) { issue(c + 1, (c + 1) & 1); CP_WAIT(1); }
        else                 { CP_WAIT(0); }
        __syncthreads();

        const char* stg = smem + (c & 1) * STGB;
        const __nv_bfloat16* Sah = (const __nv_bfloat16*)(stg);
        const __nv_bfloat16* Sal = (const __nv_bfloat16*)(stg + MATB);
        const __nv_bfloat16* Sbh = (const __nv_bfloat16*)(stg + 2 * MATB);
        const __nv_bfloat16* Sbl = (const __nv_bfloat16*)(stg + 3 * MATB);

        #pragma unroll
        for (int ks = 0; ks < 2; ks++) {
            const int kk = ks * 16;
            wmma::fragment<wmma::matrix_a, 16, 16, 16, __nv_bfloat16, wmma::row_major> ah[2], al[2];
            wmma::fragment<wmma::matrix_b, 16, 16, 16, __nv_bfloat16, wmma::col_major> bh[4], bl[4];
            #pragma unroll
            for (int i = 0; i < 2; i++) {
                wmma::load_matrix_sync(ah[i], Sah + (wm + i * 16) * LDS + kk, LDS);
                wmma::load_matrix_sync(al[i], Sal + (wm + i * 16) * LDS + kk, LDS);
            }
            #pragma unroll
            for (int j = 0; j < 4; j++) {
                wmma::load_matrix_sync(bh[j], Sbh + (wn + j * 16) * LDS + kk, LDS);
                wmma::load_matrix_sync(bl[j], Sbl + (wn + j * 16) * LDS + kk, LDS);
            }
            #pragma unroll
            for (int i = 0; i < 2; i++)
                #pragma unroll
                for (int j = 0; j < 4; j++) {
                    wmma::mma_sync(acc[i][j], ah[i], bh[j], acc[i][j]);
                    wmma::mma_sync(acc[i][j], ah[i], bl[j], acc[i][j]);
                    wmma::mma_sync(acc[i][j], al[i], bh[j], acc[i][j]);
                }
        }
        __syncthreads();
    }

    #pragma unroll
    for (int i = 0; i < 2; i++) {
        int row = m0 + wm + i * 16;
        if (row + 16 > M) continue;
        #pragma unroll
        for (int j = 0; j < 4; j++)
            wmma::store_matrix_sync(C + (size_t)row * H3 + n0 + wn + j * 16,
                                    acc[i][j], H3, wmma::mem_row_major);
    }
}

// ============================================================================
__global__ void gru_scatter_kernel(const float* __restrict__ mem,
                                   const float* __restrict__ b_ih,
                                   const float* __restrict__ b_hh,
                                   float* __restrict__ out, long long total) {
    long long i = (long long)blockIdx.x * blockDim.x + threadIdx.x;
    long long stride = (long long)gridDim.x * blockDim.x;
    for (; i < total; i += stride) {
        int u = (int)(i >> 8);
        int c = (int)(i & 255);
        int node = g_idx[u];
        if (g_win[node] != u) continue;   // last-update-wins

        const float* gi = g_gi + (size_t)u * H3;
        const float* gh = g_gh + (size_t)u * H3;
        float h = mem[(size_t)node * HDIM + c];

        float i_r = gi[c]            + __ldg(b_ih + c);
        float i_z = gi[HDIM + c]     + __ldg(b_ih + HDIM + c);
        float i_n = gi[2 * HDIM + c] + __ldg(b_ih + 2 * HDIM + c);
        float h_r = gh[c]            + __ldg(b_hh + c);
        float h_z = gh[HDIM + c]     + __ldg(b_hh + HDIM + c);
        float h_n = gh[2 * HDIM + c] + __ldg(b_hh + 2 * HDIM + c);

        float r = 1.f / (1.f + expf(-(i_r + h_r)));
        float z = 1.f / (1.f + expf(-(i_z + h_z)));
        float n = tanhf(i_n + r * h_n);
        out[(size_t)node * HDIM + c] = (1.f - z) * n + z * h;
    }
}

// ============================================================================
extern "C" void kernel_launch(void* const* d_in, const int* in_sizes, int n_in,
                              void* d_out, int out_size) {
    // resolve device addresses of scratch
    void *p;
    #define SYM(v, s) cudaGetSymbolAddress(&p, s); auto* v = decltype(&s[0])(p)
    SYM(d_gi,  g_gi);  SYM(d_gh,  g_gh);
    SYM(d_mhi, g_mhi); SYM(d_mlo, g_mlo);
    SYM(d_hhi, g_hhi); SYM(d_hlo, g_hlo);
    SYM(d_w1hi, g_w1hi); SYM(d_w1lo, g_w1lo);
    SYM(d_w2hi, g_w2hi); SYM(d_w2lo, g_w2lo);
    #undef SYM

    // size-based input identification
    const float *memory = nullptr, *messages = nullptr, *W_ih = nullptr,
                *W_hh = nullptr, *b_ih = nullptr, *b_hh = nullptr;
    const unsigned* node_raw = nullptr;
    for (int i = 0; i < n_in; i++) {
        long long s = in_sizes[i];
        const void* q = d_in[i];
        if (s == (long long)out_size)            memory   = (const float*)q;
        else if (s == (long long)H3 * MSGD)      W_ih     = (const float*)q;
        else if (s == (long long)H3 * HDIM)      W_hh     = (const float*)q;
        else if (s == H3) { if (!b_ih) b_ih = (const float*)q; else b_hh = (const float*)q; }
        else if (s == UMAX || s == 2 * UMAX)     node_raw = (const unsigned*)q;
        else if (s % MSGD == 0 && s > (long long)H3 * MSGD) messages = (const float*)q;
    }
    if (!memory)   memory   = (const float*)   d_in[0];
    if (!messages) messages = (const float*)   d_in[1];
    if (!node_raw) node_raw = (const unsigned*)d_in[2];
    if (!W_ih)     W_ih     = (const float*)   d_in[3];
    if (!W_hh)     W_hh     = (const float*)   d_in[4];
    if (!b_ih)     b_ih     = (const float*)   d_in[5];
    if (!b_hh)     b_hh     = (const float*)   d_in[6];

    const int nnodes = out_size / HDIM;
    int U = UMAX;
    for (int i = 0; i < n_in; i++)
        if (d_in[i] == (const void*)messages) { U = in_sizes[i] / MSGD; break; }

    static bool attr_done = false;
    if (!attr_done) {
        cudaFuncSetAttribute(gemm_bf16x2, cudaFuncAttributeMaxDynamicSharedMemorySize, 2 * STGB);
        attr_done = true;
    }

    cvt_idx_kernel<<<(U + 255) / 256, 256>>>(node_raw, U, nnodes);

    float* out = (float*)d_out;
    copy_out_kernel<<<2048, 256>>>((const float4*)memory, (float4*)out,
                                   (long long)out_size / 4);
    init_win_kernel<<<(nnodes + 255) / 256, 256>>>(nnodes);
    vote_kernel<<<(U + 255) / 256, 256>>>(U);

    // precompute bf16 hi/lo splits
    split_pad_kernel<<<4096, 256>>>(messages, d_mhi, d_mlo, U, MSGD, KPADM);
    split_gather_kernel<<<2048, 256>>>(memory, d_hhi, d_hlo, (long long)U * HDIM);
    split_pad_kernel<<<512, 256>>>(W_ih, d_w1hi, d_w1lo, H3, MSGD, KPADM);
    split_pad_kernel<<<512, 256>>>(W_hh, d_w2hi, d_w2lo, H3, HDIM, HDIM);

    // gi = messages @ W_ih^T   [U,768]  (Kpad=704, 22 chunks)
    {
        dim3 grid(H3 / 128, (U + 127) / 128);
        gemm_bf16x2<<<grid, 256, 2 * STGB>>>(d_mhi, d_mlo, d_w1hi, d_w1lo, d_gi,
                                             U, KPADM, KPADM / 32);
    }
    // gh = h @ W_hh^T   [U,768]  (Kpad=256, 8 chunks)
    {
        dim3 grid(H3 / 128, (U + 127) / 128);
        gemm_bf16x2<<<grid, 256, 2 * STGB>>>(d_hhi, d_hlo, d_w2hi, d_w2lo, d_gh,
                                             U, HDIM, HDIM / 32);
    }

    gru_scatter_kernel<<<4096, 256>>>(memory, b_ih, b_hh, out, (long long)U * HDIM);
}